// round 2
// baseline (speedup 1.0000x reference)
#include <cuda_runtime.h>

#define NBATCH 4
#define BLKT 256

// Transposed weights: [k][o] layout, k = h*40+m, o stride 1 (coalesced).
// Sizes: 1600*128 + 2560*128 + 2560*128 = 860160 floats (3.44 MB, static scratch).
__device__ float g_wT[860160];

__device__ __forceinline__ unsigned long long ffma2(unsigned long long a,
                                                    unsigned long long b,
                                                    unsigned long long c) {
    unsigned long long d;
    asm("fma.rn.f32x2 %0, %1, %2, %3;" : "=l"(d) : "l"(a), "l"(b), "l"(c));
    return d;
}
__device__ __forceinline__ unsigned long long pack2(float lo, float hi) {
    unsigned long long r;
    asm("mov.b64 %0, {%1, %2};" : "=l"(r) : "f"(lo), "f"(hi));
    return r;
}
__device__ __forceinline__ void unpack2(unsigned long long v, float& lo, float& hi) {
    asm("mov.b64 {%0, %1}, %2;" : "=f"(lo), "=f"(hi) : "l"(v));
}

__global__ void transpose_w_kernel(const float* __restrict__ w, int K, int dstOff) {
    int idx = blockIdx.x * blockDim.x + threadIdx.x;
    if (idx < K * 128) {
        int o = idx & 127;
        int k = idx >> 7;
        g_wT[dstOff + idx] = w[o * K + k];
    }
}

// One layer: out[nb][o][d] = relu( sum_h prev[nb][h][d] * (sum_m w[o,h,m]*x[nb][m][d]) + b[o] )
// Channels o<64 -> nextBuf (prev for next layer); o>=64 -> res[nb] += wl * sum_d(out).
// PJ = number of f32x2 pairs per thread (4 -> 8 d's, 2 -> 4 d's).
template<int H, int PJ, bool STORE>
__device__ __forceinline__ void run_layer(
    const float* __restrict__ wT,
    float bv, float wlv,
    const float* __restrict__ xS,
    const float* __restrict__ prev, int prevStride,
    float* __restrict__ nextBuf,
    float* res, int o, int d0)
{
    unsigned long long acc[NBATCH][PJ];
    #pragma unroll
    for (int nb = 0; nb < NBATCH; nb++)
        #pragma unroll
        for (int p = 0; p < PJ; p++) acc[nb][p] = 0ull;

    for (int h = 0; h < H; h++) {
        unsigned long long s[NBATCH][PJ];
        #pragma unroll
        for (int nb = 0; nb < NBATCH; nb++)
            #pragma unroll
            for (int p = 0; p < PJ; p++) s[nb][p] = 0ull;

        const float* wp = wT + h * 40 * 128 + o;
        #pragma unroll 8
        for (int m = 0; m < 40; m++) {
            float wv = __ldg(wp + m * 128);           // coalesced, L2-resident
            unsigned long long w2 = pack2(wv, wv);
            #pragma unroll
            for (int nb = 0; nb < NBATCH; nb++) {
                const float* xp = xS + nb * 640 + m * 16 + d0;
                #pragma unroll
                for (int q = 0; q < PJ / 2; q++) {
                    // broadcast LDS.128 (all lanes same address -> conflict-free)
                    ulonglong2 xv = *reinterpret_cast<const ulonglong2*>(xp + q * 4);
                    s[nb][2 * q]     = ffma2(w2, xv.x, s[nb][2 * q]);
                    s[nb][2 * q + 1] = ffma2(w2, xv.y, s[nb][2 * q + 1]);
                }
            }
        }
        #pragma unroll
        for (int nb = 0; nb < NBATCH; nb++) {
            const float* pp = prev + nb * prevStride + h * 16 + d0;
            #pragma unroll
            for (int q = 0; q < PJ / 2; q++) {
                ulonglong2 pv = *reinterpret_cast<const ulonglong2*>(pp + q * 4);
                acc[nb][2 * q]     = ffma2(pv.x, s[nb][2 * q],     acc[nb][2 * q]);
                acc[nb][2 * q + 1] = ffma2(pv.y, s[nb][2 * q + 1], acc[nb][2 * q + 1]);
            }
        }
    }

    // epilogue: bias + relu, split into prev half / direct half
    #pragma unroll
    for (int nb = 0; nb < NBATCH; nb++) {
        float sumd = 0.f;
        #pragma unroll
        for (int p = 0; p < PJ; p++) {
            float lo, hi;
            unpack2(acc[nb][p], lo, hi);
            lo = fmaxf(lo + bv, 0.f);
            hi = fmaxf(hi + bv, 0.f);
            if (STORE && o < 64) {
                nextBuf[nb * 1024 + o * 16 + d0 + 2 * p]     = lo;
                nextBuf[nb * 1024 + o * 16 + d0 + 2 * p + 1] = hi;
            }
            sumd += lo + hi;
        }
        res[nb] += wlv * sumd;   // wlv == 0 for o < 64
    }
}

__global__ __launch_bounds__(BLKT, 2) void cin_main(
    const float* __restrict__ x,
    const float* __restrict__ b0,
    const float* __restrict__ b1,
    const float* __restrict__ b2,
    const float* __restrict__ wl,
    float* __restrict__ out)
{
    __shared__ __align__(16) float xS[NBATCH * 640];    // x tiles [nb][m=40][d=16]
    __shared__ __align__(16) float pA[NBATCH * 1024];   // prev [nb][h=64][d=16]
    __shared__ __align__(16) float pB[NBATCH * 1024];
    __shared__ float red[8][NBATCH];

    int tid = threadIdx.x;
    int bb = blockIdx.x * NBATCH;

    for (int i = tid; i < NBATCH * 640; i += BLKT)
        xS[i] = x[bb * 640 + i];
    __syncthreads();

    float res[NBATCH] = {0.f, 0.f, 0.f, 0.f};

    int o  = tid & 127;
    int d0 = (tid >> 7) * 8;        // 2 d-halves of 8
    float wlv0 = (o >= 64) ? wl[o - 64]      : 0.f;
    float wlv1 = (o >= 64) ? wl[64 + o - 64] : 0.f;

    // Layer 0: H=40, prev = x itself
    run_layer<40, 4, true >(g_wT,          b0[o], wlv0, xS, xS, 640,  pA, res, o, d0);
    __syncthreads();
    // Layer 1: H=64
    run_layer<64, 4, true >(g_wT + 204800, b1[o], wlv1, xS, pA, 1024, pB, res, o, d0);
    __syncthreads();
    // Layer 2: prev-half is dead (only direct feeds output) -> all 256 threads
    // cover channels 64..127 x 4 d-groups (halves layer-2 FLOPs).
    {
        int o2  = 64 + (tid & 63);
        int d02 = (tid >> 6) * 4;   // 4 d-groups of 4
        float wlv2 = wl[128 + (tid & 63)];
        run_layer<64, 2, false>(g_wT + 532480, b2[o2], wlv2, xS, pB, 1024, nullptr,
                                res, o2, d02);
    }

    // deterministic block reduction (fixed order; no float atomics)
    int lane = tid & 31, wid = tid >> 5;
    #pragma unroll
    for (int nb = 0; nb < NBATCH; nb++) {
        float v = res[nb];
        #pragma unroll
        for (int off = 16; off > 0; off >>= 1)
            v += __shfl_xor_sync(0xffffffffu, v, off);
        if (lane == 0) red[wid][nb] = v;
    }
    __syncthreads();
    if (tid < NBATCH) {
        float t = 0.f;
        #pragma unroll
        for (int w = 0; w < 8; w++) t += red[w][tid];
        out[bb + tid] = t;
    }
}

extern "C" void kernel_launch(void* const* d_in, const int* in_sizes, int n_in,
                              void* d_out, int out_size) {
    const float* x  = (const float*)d_in[0];
    const float* w0 = (const float*)d_in[1];
    const float* b0 = (const float*)d_in[2];
    const float* w1 = (const float*)d_in[3];
    const float* b1 = (const float*)d_in[4];
    const float* w2 = (const float*)d_in[5];
    const float* b2 = (const float*)d_in[6];
    const float* wl = (const float*)d_in[7];
    float* out = (float*)d_out;

    transpose_w_kernel<<<(1600 * 128 + 255) / 256, 256>>>(w0, 1600, 0);
    transpose_w_kernel<<<(2560 * 128 + 255) / 256, 256>>>(w1, 2560, 204800);
    transpose_w_kernel<<<(2560 * 128 + 255) / 256, 256>>>(w2, 2560, 532480);

    cin_main<<<2048 / NBATCH, BLKT>>>(x, b0, b1, b2, wl, out);
}

// round 5
// speedup vs baseline: 3.3927x; 3.3927x over previous
#include <cuda_runtime.h>
#include <cuda_fp16.h>
#include <cstdint>

// smem: U[stage][pass]: 4 x 32KB, then pvS[h=64][n=256] f32 = 64KB
#define SM_U(s, p)  (((s) * 2 + (p)) * 32768)
#define SM_PV       131072
#define SM_TOTAL    196608

// W in m16n8k16 A-fragment order: [g=L*40+m][rb][ks][lane] x 8 halfs (16B)
__device__ __align__(16) __half g_wA[983040];

__device__ __forceinline__ uint32_t sh_addr(const void* p) {
    return (uint32_t)__cvta_generic_to_shared(p);
}

__device__ __forceinline__ void mma16816(float* c, const uint4& a,
                                         uint32_t bq0, uint32_t bq1) {
    asm volatile(
        "mma.sync.aligned.m16n8k16.row.col.f32.f16.f16.f32 "
        "{%0,%1,%2,%3}, {%4,%5,%6,%7}, {%8,%9}, {%0,%1,%2,%3};"
        : "+f"(c[0]), "+f"(c[1]), "+f"(c[2]), "+f"(c[3])
        : "r"(a.x), "r"(a.y), "r"(a.z), "r"(a.w), "r"(bq0), "r"(bq1));
}

// w[o][k][m] f32 (k < H real) -> g_wA fragment order, f16
__global__ void prep_w(const float* __restrict__ w, int H, int gBase) {
    int idx = blockIdx.x * blockDim.x + threadIdx.x;   // < 40*8192
    if (idx >= 40 * 8192) return;
    int e    = idx & 7;
    int lane = (idx >> 3) & 31;
    int ks   = (idx >> 8) & 3;
    int rb   = (idx >> 10) & 7;
    int m    = idx >> 13;
    int r = rb * 16 + (lane >> 2) + ((e >> 1) & 1) * 8;
    int k = ks * 16 + (lane & 3) * 2 + (e & 1) + ((e >> 2) & 1) * 8;
    float v = (k < H) ? w[r * (H * 40) + k * 40 + m] : 0.f;
    g_wA[(size_t)(gBase + m) * 8192 + (idx & 8191)] = __float2half(v);
}

__global__ void __launch_bounds__(256, 1) cin_mma(
    const float* __restrict__ x,
    const float* __restrict__ b0, const float* __restrict__ b1,
    const float* __restrict__ b2,
    const float* __restrict__ wl, float* __restrict__ out)
{
    extern __shared__ char smp[];
    float* pvS = (float*)(smp + SM_PV);          // [h][n] transposed, 1KB rows
    int t = threadIdx.x, w = t >> 5, l = t & 31;
    int bb = blockIdx.x * 16;

    const float* xcol = x + (size_t)(bb + (t >> 4)) * 640 + (t & 15);

    // layer-0 prev = x (h<40), zero-padded to 64
    #pragma unroll 4
    for (int h = 0; h < 40; h++) pvS[h * 256 + t] = xcol[h * 16];
    #pragma unroll
    for (int h = 40; h < 64; h++) pvS[h * 256 + t] = 0.f;

    float C[8][4][4];
    float acc0 = 0.f, acc1 = 0.f;
    float pv[64];

    uint32_t genRow = (uint32_t)t * 128;
    int tx7 = t & 7;
    int nBase = w * 32 + ((l >> 4) & 1) * 8 + (l & 7);   // ldmatrix row n (ntp adds 16)
    int kh = (l >> 3) & 1;
    const float* biasArr[3] = { b0, b1, b2 };

    for (int L = 0; L < 3; L++) {
        __syncthreads();                          // pvS ready (init or prev epilogue)
        #pragma unroll
        for (int h = 0; h < 64; h++) pv[h] = pvS[h * 256 + t];
        #pragma unroll
        for (int rb = 0; rb < 8; rb++)
            #pragma unroll
            for (int nt = 0; nt < 4; nt++)
                #pragma unroll
                for (int i = 0; i < 4; i++) C[rb][nt][i] = 0.f;

        int g0 = L * 40;

        // ---- chunk pipeline: gen(c) overlapped with mma(c-1) ----
        for (int c = 0; c <= 40; c++) {
            if (c > 0) __syncthreads();
            if (c < 40) {
                // generate U chunk c (hi+lo split) into buffer c&1
                float xv = __ldg(xcol + c * 16);
                char* Uh = smp + SM_U(c & 1, 0);
                char* Ul = smp + SM_U(c & 1, 1);
                #pragma unroll
                for (int j = 0; j < 8; j++) {
                    uint4 Hq, Lq;
                    uint32_t* hh = (uint32_t*)&Hq;
                    uint32_t* ll = (uint32_t*)&Lq;
                    #pragma unroll
                    for (int q = 0; q < 4; q++) {
                        float z0 = xv * pv[j * 8 + q * 2];
                        float z1 = xv * pv[j * 8 + q * 2 + 1];
                        __half2 h2 = __floats2half2_rn(z0, z1);
                        float2 hf = __half22float2(h2);
                        __half2 l2 = __floats2half2_rn(z0 - hf.x, z1 - hf.y);
                        hh[q] = *(uint32_t*)&h2;
                        ll[q] = *(uint32_t*)&l2;
                    }
                    uint32_t off = genRow + (uint32_t)((j ^ tx7) * 16);
                    *(uint4*)(Uh + off) = Hq;
                    *(uint4*)(Ul + off) = Lq;
                }
            }
            if (c > 0) {
                // MMA on chunk cc = c-1 from buffer (c-1)&1
                int cc = c - 1;
                // one chunk = 8192 halfs = 1024 uint4   (round-4 bug: was *512)
                const uint4* Ag = (const uint4*)g_wA + (size_t)(g0 + cc) * 1024;
                #pragma unroll
                for (int pass = 0; pass < 2; pass++) {
                    const char* Ub = smp + SM_U(cc & 1, pass);
                    uint32_t br[4][4][2];
                    #pragma unroll
                    for (int ks = 0; ks < 4; ks++) {
                        #pragma unroll
                        for (int ntp = 0; ntp < 2; ntp++) {
                            int n = nBase + ntp * 16;
                            uint32_t ad = sh_addr(Ub) + (uint32_t)(n * 128) +
                                          (uint32_t)((((ks * 2 + kh) ^ (n & 7)) * 16));
                            uint32_t r0, r1, r2, r3;
                            asm volatile(
                                "ldmatrix.sync.aligned.m8n8.x4.shared.b16 "
                                "{%0,%1,%2,%3}, [%4];"
                                : "=r"(r0), "=r"(r1), "=r"(r2), "=r"(r3) : "r"(ad));
                            br[ks][ntp * 2][0]     = r0;
                            br[ks][ntp * 2][1]     = r1;
                            br[ks][ntp * 2 + 1][0] = r2;
                            br[ks][ntp * 2 + 1][1] = r3;
                        }
                    }
                    #pragma unroll
                    for (int rb = 0; rb < 8; rb++) {
                        if (L == 2 && rb < 4) continue;   // dead prev-half at layer 2
                        #pragma unroll
                        for (int ks = 0; ks < 4; ks++) {
                            uint4 a = __ldg(Ag + (rb * 4 + ks) * 32 + l);
                            #pragma unroll
                            for (int nt = 0; nt < 4; nt++)
                                mma16816(C[rb][nt], a, br[ks][nt][0], br[ks][nt][1]);
                        }
                    }
                }
            }
        }

        // ---- epilogue: bias + relu; rows<64 -> pvS; rows>=64 -> wl-weighted acc ----
        const float* bp = biasArr[L];
        #pragma unroll
        for (int rb = 0; rb < 8; rb++) {
            if (L == 2 && rb < 4) continue;
            int r0 = rb * 16 + (l >> 2);
            float bv0 = __ldg(bp + r0), bv1 = __ldg(bp + r0 + 8);
            bool direct = (rb >= 4);
            float wl0 = 0.f, wl1 = 0.f;
            if (direct) {
                wl0 = __ldg(wl + L * 64 + r0 - 64);
                wl1 = __ldg(wl + L * 64 + r0 - 56);
            }
            #pragma unroll
            for (int nt = 0; nt < 4; nt++) {
                int n0 = w * 32 + nt * 8 + (l & 3) * 2;
                float v0 = fmaxf(C[rb][nt][0] + bv0, 0.f);
                float v1 = fmaxf(C[rb][nt][1] + bv0, 0.f);
                float v2 = fmaxf(C[rb][nt][2] + bv1, 0.f);
                float v3 = fmaxf(C[rb][nt][3] + bv1, 0.f);
                if (!direct) {
                    if (L < 2) {
                        pvS[r0 * 256 + n0]           = v0;
                        pvS[r0 * 256 + n0 + 1]       = v1;
                        pvS[(r0 + 8) * 256 + n0]     = v2;
                        pvS[(r0 + 8) * 256 + n0 + 1] = v3;
                    }
                } else {
                    float a = wl0 * (v0 + v1) + wl1 * (v2 + v3);
                    if (nt < 2) acc0 += a; else acc1 += a;
                }
            }
        }
    }

    // deterministic warp reduction; warp w owns batches 2w, 2w+1
    #pragma unroll
    for (int off = 16; off > 0; off >>= 1) {
        acc0 += __shfl_xor_sync(0xffffffffu, acc0, off);
        acc1 += __shfl_xor_sync(0xffffffffu, acc1, off);
    }
    if (l == 0) {
        out[bb + 2 * w]     = acc0;
        out[bb + 2 * w + 1] = acc1;
    }
}

extern "C" void kernel_launch(void* const* d_in, const int* in_sizes, int n_in,
                              void* d_out, int out_size) {
    const float* x  = (const float*)d_in[0];
    const float* w0 = (const float*)d_in[1];
    const float* b0 = (const float*)d_in[2];
    const float* w1 = (const float*)d_in[3];
    const float* b1 = (const float*)d_in[4];
    const float* w2 = (const float*)d_in[5];
    const float* b2 = (const float*)d_in[6];
    const float* wl = (const float*)d_in[7];
    float* out = (float*)d_out;

    cudaFuncSetAttribute(cin_mma, cudaFuncAttributeMaxDynamicSharedMemorySize,
                         SM_TOTAL);

    int np = 40 * 8192;
    prep_w<<<(np + 255) / 256, 256>>>(w0, 40, 0);
    prep_w<<<(np + 255) / 256, 256>>>(w1, 64, 40);
    prep_w<<<(np + 255) / 256, 256>>>(w2, 64, 80);

    cin_mma<<<128, 256, SM_TOTAL>>>(x, b0, b1, b2, wl, out);
}

// round 6
// speedup vs baseline: 4.3896x; 1.2939x over previous
#include <cuda_runtime.h>
#include <cuda_fp16.h>
#include <cstdint>

#define SM_U(s)   ((s) * 32768)      // U double buffer: 2 x 32KB  [n=256][k=64] f16, swizzled
#define SM_PV     65536              // prev [h=64][n=256] f32 = 64KB
#define SM_RED    131072             // 32 f32
#define SM_TOTAL  131200

// W in m16n8k16 A-fragment order: [g=L*40+m][rb][ks][lane] x 8 halfs (16B)
__device__ __align__(16) __half g_wA[983040];

__device__ __forceinline__ uint32_t sh_addr(const void* p) {
    return (uint32_t)__cvta_generic_to_shared(p);
}

__device__ __forceinline__ void mma16816(float* c, const uint4& a,
                                         uint32_t bq0, uint32_t bq1) {
    asm volatile(
        "mma.sync.aligned.m16n8k16.row.col.f32.f16.f16.f32 "
        "{%0,%1,%2,%3}, {%4,%5,%6,%7}, {%8,%9}, {%0,%1,%2,%3};"
        : "+f"(c[0]), "+f"(c[1]), "+f"(c[2]), "+f"(c[3])
        : "r"(a.x), "r"(a.y), "r"(a.z), "r"(a.w), "r"(bq0), "r"(bq1));
}

#define LDMX4(r0, r1, r2, r3, ad) \
    asm volatile("ldmatrix.sync.aligned.m8n8.x4.shared.b16 {%0,%1,%2,%3}, [%4];" \
        : "=r"(r0), "=r"(r1), "=r"(r2), "=r"(r3) : "r"(ad))

// w[o][k][m] f32 (k < H real) -> g_wA fragment order, f16
__global__ void prep_w(const float* __restrict__ w, int H, int gBase) {
    int idx = blockIdx.x * blockDim.x + threadIdx.x;   // < 40*8192
    if (idx >= 40 * 8192) return;
    int e    = idx & 7;
    int lane = (idx >> 3) & 31;
    int ks   = (idx >> 8) & 3;
    int rb   = (idx >> 10) & 7;
    int m    = idx >> 13;
    int r = rb * 16 + (lane >> 2) + ((e >> 1) & 1) * 8;
    int k = ks * 16 + (lane & 3) * 2 + (e & 1) + ((e >> 2) & 1) * 8;
    float v = (k < H) ? w[r * (H * 40) + k * 40 + m] : 0.f;
    g_wA[(size_t)(gBase + m) * 8192 + (idx & 8191)] = __float2half(v);
}

__global__ void __launch_bounds__(512, 1) cin_mma(
    const float* __restrict__ x,
    const float* __restrict__ b0, const float* __restrict__ b1,
    const float* __restrict__ b2,
    const float* __restrict__ wl, float* __restrict__ out)
{
    extern __shared__ char smp[];
    float* pvS = (float*)(smp + SM_PV);
    float* red = (float*)(smp + SM_RED);
    int t = threadIdx.x, w = t >> 5, l = t & 31;
    int bb = blockIdx.x * 16;

    // ---- gen mapping: thread covers column gn, k-range [gh, gh+32) ----
    int gn = t & 255;
    int gh = (t >> 8) * 32;
    const float* xcolg = x + (size_t)(bb + (gn >> 4)) * 640 + (gn & 15);

    float pv[32];                       // prev slice for this half-column
    #pragma unroll
    for (int i = 0; i < 32; i++) {
        int h = gh + i;
        pv[i] = (h < 40) ? __ldg(xcolg + h * 16) : 0.f;   // layer-0 prev = x
    }

    uint32_t goff[4];
    #pragma unroll
    for (int j = 0; j < 4; j++)
        goff[j] = (uint32_t)(gn * 128 + ((((gh >> 3) + j) ^ (gn & 7)) * 16));

    // ---- MMA mapping: warp tile = 64 rows (rg) x 32 cols (cg); L2: 64x16 ----
    int rg = w >> 3, cg = w & 7;
    int kh = (l >> 3) & 1;
    int lrow = ((l >> 4) & 1) * 8 + (l & 7);

    float C[4][4][4];
    float accA0 = 0.f, accA1 = 0.f, accL2 = 0.f;
    const float* biasArr[3] = { b0, b1, b2 };

    for (int L = 0; L < 3; L++) {
        bool isL2 = (L == 2);
        #pragma unroll
        for (int rbi = 0; rbi < 4; rbi++)
            #pragma unroll
            for (int nt = 0; nt < 4; nt++)
                #pragma unroll
                for (int i = 0; i < 4; i++) C[rbi][nt][i] = 0.f;
        int g0 = L * 40;

        for (int c = 0; c <= 40; c++) {
            __syncthreads();
            if (c < 40) {                       // generate U chunk c -> buf c&1
                float xv = __ldg(xcolg + c * 16);
                char* Ub = smp + SM_U(c & 1);
                #pragma unroll
                for (int j = 0; j < 4; j++) {
                    uint4 Hq; uint32_t* hh = (uint32_t*)&Hq;
                    #pragma unroll
                    for (int q = 0; q < 4; q++) {
                        __half2 h2 = __floats2half2_rn(xv * pv[j * 8 + q * 2],
                                                       xv * pv[j * 8 + q * 2 + 1]);
                        hh[q] = *(uint32_t*)&h2;
                    }
                    *(uint4*)(Ub + goff[j]) = Hq;
                }
            }
            if (c > 0) {                        // MMA chunk c-1 from buf (c-1)&1
                int cc = c - 1;
                uint32_t ub = sh_addr(smp + SM_U(cc & 1));
                const uint4* Ag = (const uint4*)g_wA + (size_t)(g0 + cc) * 1024;
                if (!isL2) {
                    #pragma unroll
                    for (int ks = 0; ks < 4; ks++) {
                        uint32_t br[4][2];
                        #pragma unroll
                        for (int ntp = 0; ntp < 2; ntp++) {
                            int n = cg * 32 + ntp * 16 + lrow;
                            uint32_t ad = ub + (uint32_t)(n * 128) +
                                          (uint32_t)((((ks * 2 + kh) ^ (n & 7)) * 16));
                            LDMX4(br[ntp * 2][0], br[ntp * 2][1],
                                  br[ntp * 2 + 1][0], br[ntp * 2 + 1][1], ad);
                        }
                        #pragma unroll
                        for (int rbi = 0; rbi < 4; rbi++) {
                            uint4 a = __ldg(Ag + (((rg * 4 + rbi) * 4 + ks) * 32) + l);
                            #pragma unroll
                            for (int nt = 0; nt < 4; nt++)
                                mma16816(C[rbi][nt], a, br[nt][0], br[nt][1]);
                        }
                    }
                } else {                        // rows 64..127, cols w*16..+16
                    #pragma unroll
                    for (int ks = 0; ks < 4; ks++) {
                        uint32_t br[2][2];
                        int n = w * 16 + lrow;
                        uint32_t ad = ub + (uint32_t)(n * 128) +
                                      (uint32_t)((((ks * 2 + kh) ^ (n & 7)) * 16));
                        LDMX4(br[0][0], br[0][1], br[1][0], br[1][1], ad);
                        #pragma unroll
                        for (int rbi = 0; rbi < 4; rbi++) {
                            uint4 a = __ldg(Ag + (((4 + rbi) * 4 + ks) * 32) + l);
                            #pragma unroll
                            for (int nt = 0; nt < 2; nt++)
                                mma16816(C[rbi][nt], a, br[nt][0], br[nt][1]);
                        }
                    }
                }
            }
        }

        // ---- epilogue ----
        const float* bp = biasArr[L];
        if (!isL2) {
            #pragma unroll
            for (int rbi = 0; rbi < 4; rbi++) {
                int r0 = (rg * 4 + rbi) * 16 + (l >> 2);
                float bv0 = __ldg(bp + r0), bv1 = __ldg(bp + r0 + 8);
                float wl0 = 0.f, wl1 = 0.f;
                if (rg == 1) {
                    wl0 = __ldg(wl + L * 64 + r0 - 64);
                    wl1 = __ldg(wl + L * 64 + r0 - 56);
                }
                #pragma unroll
                for (int nt = 0; nt < 4; nt++) {
                    int n0 = cg * 32 + nt * 8 + (l & 3) * 2;
                    float v0 = fmaxf(C[rbi][nt][0] + bv0, 0.f);
                    float v1 = fmaxf(C[rbi][nt][1] + bv0, 0.f);
                    float v2 = fmaxf(C[rbi][nt][2] + bv1, 0.f);
                    float v3 = fmaxf(C[rbi][nt][3] + bv1, 0.f);
                    if (rg == 0) {              // prev half -> pvS
                        pvS[r0 * 256 + n0]           = v0;
                        pvS[r0 * 256 + n0 + 1]       = v1;
                        pvS[(r0 + 8) * 256 + n0]     = v2;
                        pvS[(r0 + 8) * 256 + n0 + 1] = v3;
                    } else {                    // direct half -> weighted acc
                        float a = wl0 * (v0 + v1) + wl1 * (v2 + v3);
                        if (nt < 2) accA0 += a; else accA1 += a;
                    }
                }
            }
            __syncthreads();                    // pvS writes visible
            #pragma unroll
            for (int i = 0; i < 32; i++) pv[i] = pvS[(gh + i) * 256 + gn];
        } else {
            #pragma unroll
            for (int rbi = 0; rbi < 4; rbi++) {
                int r0 = (4 + rbi) * 16 + (l >> 2);
                float bv0 = __ldg(bp + r0), bv1 = __ldg(bp + r0 + 8);
                float wl0 = __ldg(wl + 128 + r0 - 64);
                float wl1 = __ldg(wl + 128 + r0 - 56);
                #pragma unroll
                for (int nt = 0; nt < 2; nt++) {
                    float v0 = fmaxf(C[rbi][nt][0] + bv0, 0.f);
                    float v1 = fmaxf(C[rbi][nt][1] + bv0, 0.f);
                    float v2 = fmaxf(C[rbi][nt][2] + bv1, 0.f);
                    float v3 = fmaxf(C[rbi][nt][3] + bv1, 0.f);
                    accL2 += wl0 * (v0 + v1) + wl1 * (v2 + v3);
                }
            }
        }
    }

    // ---- deterministic reduction ----
    #pragma unroll
    for (int off = 16; off > 0; off >>= 1) {
        accA0 += __shfl_xor_sync(0xffffffffu, accA0, off);
        accA1 += __shfl_xor_sync(0xffffffffu, accA1, off);
        accL2 += __shfl_xor_sync(0xffffffffu, accL2, off);
    }
    __syncthreads();
    if (l == 0) {
        if (rg == 1) { red[2 * cg] = accA0; red[2 * cg + 1] = accA1; }
        red[16 + w] = accL2;
    }
    __syncthreads();
    if (t < 16) out[bb + t] = red[t] + red[16 + t];
}

extern "C" void kernel_launch(void* const* d_in, const int* in_sizes, int n_in,
                              void* d_out, int out_size) {
    const float* x  = (const float*)d_in[0];
    const float* w0 = (const float*)d_in[1];
    const float* b0 = (const float*)d_in[2];
    const float* w1 = (const float*)d_in[3];
    const float* b1 = (const float*)d_in[4];
    const float* w2 = (const float*)d_in[5];
    const float* b2 = (const float*)d_in[6];
    const float* wl = (const float*)d_in[7];
    float* out = (float*)d_out;

    cudaFuncSetAttribute(cin_mma, cudaFuncAttributeMaxDynamicSharedMemorySize,
                         SM_TOTAL);

    int np = 40 * 8192;
    prep_w<<<(np + 255) / 256, 256>>>(w0, 40, 0);
    prep_w<<<(np + 255) / 256, 256>>>(w1, 64, 40);
    prep_w<<<(np + 255) / 256, 256>>>(w2, 64, 80);

    cin_mma<<<128, 512, SM_TOTAL>>>(x, b0, b1, b2, wl, out);
}

// round 7
// speedup vs baseline: 8.3695x; 1.9066x over previous
#include <cuda_runtime.h>
#include <cuda_fp16.h>
#include <cstdint>

// smem: U ring 3 x 32KB, A ring 3 x 16KB, pvS 64KB, red
#define SM_U(s)   ((s) * 32768)              // [n=256][k=64] f16, swizzled
#define SM_A(s)   (98304 + (s) * 16384)      // A chunk staged linear
#define SM_PV     147456                     // prev [h=64][n=256] f32
#define SM_RED    212992                     // 32 f32
#define SM_TOTAL  213120

// W in m16n8k16 A-fragment order: [g=L*40+m][rb][ks][lane] x 8 halfs (16B)
__device__ __align__(16) __half g_wA[983040];

__device__ __forceinline__ uint32_t sh_addr(const void* p) {
    return (uint32_t)__cvta_generic_to_shared(p);
}

__device__ __forceinline__ void mma16816(float* c, const uint4& a,
                                         uint32_t bq0, uint32_t bq1) {
    asm volatile(
        "mma.sync.aligned.m16n8k16.row.col.f32.f16.f16.f32 "
        "{%0,%1,%2,%3}, {%4,%5,%6,%7}, {%8,%9}, {%0,%1,%2,%3};"
        : "+f"(c[0]), "+f"(c[1]), "+f"(c[2]), "+f"(c[3])
        : "r"(a.x), "r"(a.y), "r"(a.z), "r"(a.w), "r"(bq0), "r"(bq1));
}

#define LDMX4(r0, r1, r2, r3, ad) \
    asm volatile("ldmatrix.sync.aligned.m8n8.x4.shared.b16 {%0,%1,%2,%3}, [%4];" \
        : "=r"(r0), "=r"(r1), "=r"(r2), "=r"(r3) : "r"(ad))

#define CPA16(dst, src) \
    asm volatile("cp.async.cg.shared.global [%0], [%1], 16;" :: "r"(dst), "l"(src))

// w[o][k][m] f32 (k < H real) -> g_wA fragment order, f16
__global__ void prep_w(const float* __restrict__ w, int H, int gBase) {
    int idx = blockIdx.x * blockDim.x + threadIdx.x;   // < 40*8192
    if (idx >= 40 * 8192) return;
    int e    = idx & 7;
    int lane = (idx >> 3) & 31;
    int ks   = (idx >> 8) & 3;
    int rb   = (idx >> 10) & 7;
    int m    = idx >> 13;
    int r = rb * 16 + (lane >> 2) + ((e >> 1) & 1) * 8;
    int k = ks * 16 + (lane & 3) * 2 + (e & 1) + ((e >> 2) & 1) * 8;
    float v = (k < H) ? w[r * (H * 40) + k * 40 + m] : 0.f;
    g_wA[(size_t)(gBase + m) * 8192 + (idx & 8191)] = __float2half(v);
}

__global__ void __launch_bounds__(512, 1) cin_mma(
    const float* __restrict__ x,
    const float* __restrict__ b0, const float* __restrict__ b1,
    const float* __restrict__ b2,
    const float* __restrict__ wl, float* __restrict__ out)
{
    extern __shared__ char smp[];
    float* pvS = (float*)(smp + SM_PV);
    float* red = (float*)(smp + SM_RED);
    int t = threadIdx.x, w = t >> 5, l = t & 31;
    int bb = blockIdx.x * 16;

    // ---- gen mapping: thread covers column gn, k-range [gh, gh+32) ----
    int gn = t & 255;
    int gh = (t >> 8) * 32;
    const float* xcolg = x + (size_t)(bb + (gn >> 4)) * 640 + (gn & 15);

    float pv[32];
    #pragma unroll
    for (int i = 0; i < 32; i++) {
        int h = gh + i;
        pv[i] = (h < 40) ? __ldg(xcolg + h * 16) : 0.f;   // layer-0 prev = x
    }

    uint32_t goff[4];
    #pragma unroll
    for (int j = 0; j < 4; j++)
        goff[j] = (uint32_t)(gn * 128 + ((((gh >> 3) + j) ^ (gn & 7)) * 16));

    // ---- MMA mapping: warp tile = 64 rows (rg) x 32 cols (cg); L2: 64x16 ----
    int rg = w >> 3, cg = w & 7;
    int kh = (l >> 3) & 1;
    int lrow = ((l >> 4) & 1) * 8 + (l & 7);

    float C[4][4][4];
    float accA0 = 0.f, accA1 = 0.f, accL2 = 0.f;
    const float* biasArr[3] = { b0, b1, b2 };

    for (int L = 0; L < 3; L++) {
        bool isL2 = (L == 2);
        #pragma unroll
        for (int rbi = 0; rbi < 4; rbi++)
            #pragma unroll
            for (int nt = 0; nt < 4; nt++)
                #pragma unroll
                for (int i = 0; i < 4; i++) C[rbi][nt][i] = 0.f;
        int g0 = L * 40;

        for (int c = 0; c <= 40; c++) {
            if (c < 40) {
                // prefetch A(c) into ring slot c%3 (consumed next iteration)
                const char* src = (const char*)g_wA + (size_t)(g0 + c) * 16384 + t * 16;
                uint32_t dst = sh_addr(smp + SM_A(c % 3)) + (uint32_t)(t * 16);
                CPA16(dst, src);
                CPA16(dst + 8192, src + 8192);
                asm volatile("cp.async.commit_group;" ::: "memory");

                // generate U chunk c -> ring slot c%3
                float xv = __ldg(xcolg + c * 16);
                char* Ub = smp + SM_U(c % 3);
                #pragma unroll
                for (int j = 0; j < 4; j++) {
                    uint4 Hq; uint32_t* hh = (uint32_t*)&Hq;
                    #pragma unroll
                    for (int q = 0; q < 4; q++) {
                        __half2 h2 = __floats2half2_rn(xv * pv[j * 8 + q * 2],
                                                       xv * pv[j * 8 + q * 2 + 1]);
                        hh[q] = *(uint32_t*)&h2;
                    }
                    *(uint4*)(Ub + goff[j]) = Hq;
                }
                // own A(c-1) group complete; A(c) stays in flight
                asm volatile("cp.async.wait_group 1;" ::: "memory");
            } else {
                asm volatile("cp.async.wait_group 0;" ::: "memory");
            }
            __syncthreads();   // all copies/gen of (c-1) visible; ring reuse safe (mod 3)

            if (c > 0) {
                int cc = c - 1;
                uint32_t ub = sh_addr(smp + SM_U(cc % 3));
                const char* Ab = smp + SM_A(cc % 3);
                if (!isL2) {
                    #pragma unroll
                    for (int ks = 0; ks < 4; ks++) {
                        uint32_t br[4][2];
                        #pragma unroll
                        for (int ntp = 0; ntp < 2; ntp++) {
                            int n = cg * 32 + ntp * 16 + lrow;
                            uint32_t ad = ub + (uint32_t)(n * 128) +
                                          (uint32_t)((((ks * 2 + kh) ^ (n & 7)) * 16));
                            LDMX4(br[ntp * 2][0], br[ntp * 2][1],
                                  br[ntp * 2 + 1][0], br[ntp * 2 + 1][1], ad);
                        }
                        #pragma unroll
                        for (int rbi = 0; rbi < 4; rbi++) {
                            uint4 a = *(const uint4*)(Ab +
                                (((rg * 4 + rbi) * 4 + ks) * 32 + l) * 16);
                            #pragma unroll
                            for (int nt = 0; nt < 4; nt++)
                                mma16816(C[rbi][nt], a, br[nt][0], br[nt][1]);
                        }
                    }
                } else {                        // rows 64..127, cols w*16..+16
                    #pragma unroll
                    for (int ks = 0; ks < 4; ks++) {
                        uint32_t br[2][2];
                        int n = w * 16 + lrow;
                        uint32_t ad = ub + (uint32_t)(n * 128) +
                                      (uint32_t)((((ks * 2 + kh) ^ (n & 7)) * 16));
                        LDMX4(br[0][0], br[0][1], br[1][0], br[1][1], ad);
                        #pragma unroll
                        for (int rbi = 0; rbi < 4; rbi++) {
                            uint4 a = *(const uint4*)(Ab +
                                (((4 + rbi) * 4 + ks) * 32 + l) * 16);
                            #pragma unroll
                            for (int nt = 0; nt < 2; nt++)
                                mma16816(C[rbi][nt], a, br[nt][0], br[nt][1]);
                        }
                    }
                }
            }
        }

        // ---- epilogue ----
        const float* bp = biasArr[L];
        if (!isL2) {
            #pragma unroll
            for (int rbi = 0; rbi < 4; rbi++) {
                int r0 = (rg * 4 + rbi) * 16 + (l >> 2);
                float bv0 = __ldg(bp + r0), bv1 = __ldg(bp + r0 + 8);
                float wl0 = 0.f, wl1 = 0.f;
                if (rg == 1) {
                    wl0 = __ldg(wl + L * 64 + r0 - 64);
                    wl1 = __ldg(wl + L * 64 + r0 - 56);
                }
                #pragma unroll
                for (int nt = 0; nt < 4; nt++) {
                    int n0 = cg * 32 + nt * 8 + (l & 3) * 2;
                    float v0 = fmaxf(C[rbi][nt][0] + bv0, 0.f);
                    float v1 = fmaxf(C[rbi][nt][1] + bv0, 0.f);
                    float v2 = fmaxf(C[rbi][nt][2] + bv1, 0.f);
                    float v3 = fmaxf(C[rbi][nt][3] + bv1, 0.f);
                    if (rg == 0) {              // prev half -> pvS
                        pvS[r0 * 256 + n0]           = v0;
                        pvS[r0 * 256 + n0 + 1]       = v1;
                        pvS[(r0 + 8) * 256 + n0]     = v2;
                        pvS[(r0 + 8) * 256 + n0 + 1] = v3;
                    } else {                    // direct half -> weighted acc
                        float a = wl0 * (v0 + v1) + wl1 * (v2 + v3);
                        if (nt < 2) accA0 += a; else accA1 += a;
                    }
                }
            }
            __syncthreads();                    // pvS writes visible
            #pragma unroll
            for (int i = 0; i < 32; i++) pv[i] = pvS[(gh + i) * 256 + gn];
        } else {
            #pragma unroll
            for (int rbi = 0; rbi < 4; rbi++) {
                int r0 = (4 + rbi) * 16 + (l >> 2);
                float bv0 = __ldg(bp + r0), bv1 = __ldg(bp + r0 + 8);
                float wl0 = __ldg(wl + 128 + r0 - 64);
                float wl1 = __ldg(wl + 128 + r0 - 56);
                #pragma unroll
                for (int nt = 0; nt < 2; nt++) {
                    float v0 = fmaxf(C[rbi][nt][0] + bv0, 0.f);
                    float v1 = fmaxf(C[rbi][nt][1] + bv0, 0.f);
                    float v2 = fmaxf(C[rbi][nt][2] + bv1, 0.f);
                    float v3 = fmaxf(C[rbi][nt][3] + bv1, 0.f);
                    accL2 += wl0 * (v0 + v1) + wl1 * (v2 + v3);
                }
            }
        }
    }

    // ---- deterministic reduction ----
    #pragma unroll
    for (int off = 16; off > 0; off >>= 1) {
        accA0 += __shfl_xor_sync(0xffffffffu, accA0, off);
        accA1 += __shfl_xor_sync(0xffffffffu, accA1, off);
        accL2 += __shfl_xor_sync(0xffffffffu, accL2, off);
    }
    __syncthreads();
    if (l == 0) {
        if (rg == 1) { red[2 * cg] = accA0; red[2 * cg + 1] = accA1; }
        red[16 + w] = accL2;
    }
    __syncthreads();
    if (t < 16) out[bb + t] = red[t] + red[16 + t];
}

extern "C" void kernel_launch(void* const* d_in, const int* in_sizes, int n_in,
                              void* d_out, int out_size) {
    const float* x  = (const float*)d_in[0];
    const float* w0 = (const float*)d_in[1];
    const float* b0 = (const float*)d_in[2];
    const float* w1 = (const float*)d_in[3];
    const float* b1 = (const float*)d_in[4];
    const float* w2 = (const float*)d_in[5];
    const float* b2 = (const float*)d_in[6];
    const float* wl = (const float*)d_in[7];
    float* out = (float*)d_out;

    cudaFuncSetAttribute(cin_mma, cudaFuncAttributeMaxDynamicSharedMemorySize,
                         SM_TOTAL);

    int np = 40 * 8192;
    prep_w<<<(np + 255) / 256, 256>>>(w0, 40, 0);
    prep_w<<<(np + 255) / 256, 256>>>(w1, 64, 40);
    prep_w<<<(np + 255) / 256, 256>>>(w2, 64, 80);

    cin_mma<<<128, 512, SM_TOTAL>>>(x, b0, b1, b2, wl, out);
}